// round 13
// baseline (speedup 1.0000x reference)
#include <cuda_runtime.h>
#include <cuda_fp16.h>
#include <cstdint>

#define DD    256
#define KK    8192
#define NTOK  16384
#define HWSZ  1024
#define QSIZE 4194304
// out layout: [quantized (QSIZE) | loss (1) | indices (NTOK)] fp32 (confirmed R1/R3/R6)

__device__ __align__(16) unsigned char g_embB[KK * DD * 2];  // 4MB pre-swizzled fp16 chunk blobs
__device__ float  g_c[KK];           // exact ||e_k||^2
__device__ float  g_loss;
__device__ unsigned g_done;

// ---- smem byte offsets (M=128 tile, 2-stage x 64KB bulk ring) ----
#define SM_A     0                // 128 rows x 528B = 67584
#define SM_B     67584            // 2 stages x 65536 = 131072
#define SM_MBAR  198656           // 2 mbarriers (pad 64)
#define SM_PACK  198720           // u64[128] = 1024
#define SM_CAND  199744           // u32[2048] = 8192
#define SM_BEST  207936           // u32[128] = 512
#define SMEM_BYTES 208448

// ---------------- helpers ----------------
__device__ __forceinline__ uint32_t smem_u32(const void* p) {
    uint32_t a;
    asm("{ .reg .u64 t; cvta.to.shared.u64 t, %1; cvt.u32.u64 %0, t; }" : "=r"(a) : "l"(p));
    return a;
}
__device__ __forceinline__ void mbar_init(uint32_t mbar, uint32_t cnt) {
    asm volatile("mbarrier.init.shared.b64 [%0], %1;" :: "r"(mbar), "r"(cnt) : "memory");
}
__device__ __forceinline__ void mbar_expect_tx(uint32_t mbar, uint32_t tx) {
    asm volatile("mbarrier.arrive.expect_tx.shared.b64 _, [%0], %1;" :: "r"(mbar), "r"(tx) : "memory");
}
__device__ __forceinline__ void mwait(uint32_t mbar, uint32_t ph) {
    uint32_t done = 0;
    while (!done)
        asm volatile("{ .reg .pred p; mbarrier.try_wait.parity.shared.b64 p, [%1], %2, 0x989680; selp.b32 %0,1,0,p; }"
                     : "=r"(done) : "r"(mbar), "r"(ph) : "memory");
}
__device__ __forceinline__ void bulkcp(uint32_t dst, const void* src, uint32_t bytes, uint32_t mbar) {
    asm volatile("cp.async.bulk.shared::cluster.global.mbarrier::complete_tx::bytes [%0], [%1], %2, [%3];"
                 :: "r"(dst), "l"(src), "r"(bytes), "r"(mbar) : "memory");
}
__device__ __forceinline__ void ldsm4(uint32_t& r0, uint32_t& r1, uint32_t& r2, uint32_t& r3,
                                      uint32_t addr) {
    asm volatile("ldmatrix.sync.aligned.m8n8.x4.shared.b16 {%0,%1,%2,%3}, [%4];"
                 : "=r"(r0), "=r"(r1), "=r"(r2), "=r"(r3) : "r"(addr));
}
// f16-accumulate MMA: D/C = 2 regs (4 halves)
__device__ __forceinline__ void mma16816h(uint32_t* d, const uint32_t* a, const uint32_t* b) {
    asm volatile("mma.sync.aligned.m16n8k16.row.col.f16.f16.f16.f16 "
                 "{%0,%1},{%2,%3,%4,%5},{%6,%7},{%0,%1};"
                 : "+r"(d[0]), "+r"(d[1])
                 : "r"(a[0]), "r"(a[1]), "r"(a[2]), "r"(a[3]), "r"(b[0]), "r"(b[1]));
}

// ---------------- prep: emb -> swizzled fp16 chunk blobs + ||e||^2 ----------------
// 16KB sub-chunk c = (ct*4+kc). Byte for (code n, seg of 8 halves):
//   c*16384 + n*128 + ((seg*16) ^ ((n&7)*16))
// 64KB big-chunk ct = sub-chunks 4ct..4ct+3 (contiguous) = 128 codes x 256 dims.
__global__ void prep_all(const float* __restrict__ emb) {
    const int gid = blockIdx.x * 256 + threadIdx.x;    // 1024 blocks -> 262144 threads
    const int k = gid >> 5, r5 = gid & 31;             // one warp per code k
    const int kc = r5 >> 3, seg = r5 & 7;
    const int n = k & 127, ct = k >> 7;
    const float4* src = (const float4*)(emb + (size_t)k * DD + kc * 64 + seg * 8);
    float4 f0 = src[0], f1 = src[1];
    __half2 h01 = __floats2half2_rn(f0.x, f0.y);
    __half2 h23 = __floats2half2_rn(f0.z, f0.w);
    __half2 h45 = __floats2half2_rn(f1.x, f1.y);
    __half2 h67 = __floats2half2_rn(f1.z, f1.w);
    uint4 pack;
    pack.x = *(uint32_t*)&h01; pack.y = *(uint32_t*)&h23;
    pack.z = *(uint32_t*)&h45; pack.w = *(uint32_t*)&h67;
    uint32_t off = (uint32_t)((ct * 4 + kc) << 14) + (uint32_t)(n * 128)
                 + (((uint32_t)seg * 16) ^ ((uint32_t)(n & 7) * 16));
    *(uint4*)(g_embB + off) = pack;

    float s = f0.x*f0.x + f0.y*f0.y + f0.z*f0.z + f0.w*f0.w
            + f1.x*f1.x + f1.y*f1.y + f1.z*f1.z + f1.w*f1.w;
#pragma unroll
    for (int o = 16; o > 0; o >>= 1) s += __shfl_xor_sync(0xffffffffu, s, o);
    if (r5 == 0) g_c[k] = s;
    if (gid == 0) { g_loss = 0.f; g_done = 0u; }
}

// ---------------- main: M=128, 128 CTAs x 256 thr, 2-stage 64KB pipeline, f16 acc ----------------
__global__ void __launch_bounds__(256, 1) vq_main(const float* __restrict__ x,
                                                  const float* __restrict__ emb,
                                                  float* __restrict__ out) {
    extern __shared__ __align__(128) char sm[];
    const uint32_t base = smem_u32(sm);

    unsigned long long* sPack = (unsigned long long*)(sm + SM_PACK);
    uint32_t* sCand = (uint32_t*)(sm + SM_CAND);
    uint32_t* sBest = (uint32_t*)(sm + SM_BEST);
    const uint32_t mb = base + SM_MBAR;

    const int tid = threadIdx.x, lane = tid & 31, wid = tid >> 5;
    const int wr = wid >> 1, wc = wid & 1;            // 4 warp-rows x 2 warp-cols
    const int m0 = blockIdx.x * 128, b = m0 >> 10, hw0 = m0 & 1023;
    const float* Ag = x + (size_t)b * DD * HWSZ + hw0;   // Ag[d*1024 + token]

    if (tid == 0) {
        mbar_init(mb + 0, 1); mbar_init(mb + 8, 1);
        asm volatile("fence.proxy.async.shared::cta;" ::: "memory");
    }

    // ---- build A smem [token][k] fp16 (row stride 264 halves = 528B) ----
#pragma unroll 4
    for (int it = 0; it < 64; ++it) {
        int i  = tid + it * 256;            // 0..16383
        int dp = i >> 7, r = i & 127;       // dp = d-pair 0..127, r = token 0..127
        float v0 = Ag[(size_t)(2 * dp) * HWSZ + r];
        float v1 = Ag[(size_t)(2 * dp + 1) * HWSZ + r];
        __half2 h2 = __floats2half2_rn(v0, v1);
        *(uint32_t*)(sm + SM_A + r * 528 + dp * 4) = *(uint32_t*)&h2;
    }
    __syncthreads();   // mbar init + A visible

    // ---- prefetch big-chunks 0,1 into stages 0,1 (one 64KB bulk DMA each) ----
    if (tid == 0) {
#pragma unroll
        for (int c = 0; c < 2; ++c) {
            mbar_expect_tx(mb + c * 8, 65536);
            bulkcp(base + SM_B + (uint32_t)c * 65536, g_embB + (size_t)c * 65536, 65536, mb + c * 8);
        }
    }

    // ---- precomputed ldmatrix addresses ----
    const int i8 = lane & 7, g = lane >> 3;
    uint32_t aBase[2];
#pragma unroll
    for (int t = 0; t < 2; ++t) {
        int rowA = wr * 32 + t * 16 + (g & 1) * 8 + i8;
        aBase[t] = base + SM_A + rowA * 528 + (g >> 1) * 16;
    }
    uint32_t bBase[4], bXor[4];
    const uint32_t kadd = (g & 1) * 16;
#pragma unroll
    for (int up = 0; up < 4; ++up) {
        int n = wc * 64 + up * 16 + ((g >> 1) ? 8 : 0) + i8;
        bBase[up] = base + SM_B + n * 128;
        bXor[up]  = (uint32_t)((n & 7) * 16);
    }

    uint32_t acc[2][8][2];                 // f16x2 accumulators
    const float INF = __int_as_float(0x7f800000);
    float m1f[4] = {INF, INF, INF, INF}, m2f[4] = {INF, INF, INF, INF};
    int   m1i[4] = {0, 0, 0, 0},        m2i[4] = {0, 0, 0, 0};
    const int ac = lane & 3;
    uint32_t pf0 = 0, pf1 = 0;
    const int ksrev = (wid & 1) ? 15 : 0;  // warp-parity ks stagger

    for (int ct = 0; ct < 64; ++ct) {      // big-chunk = full ct: 128 codes x 256 dims (64KB)
        const int st = ct & 1;
        if (st == 0) { mwait(mb + 0, pf0); pf0 ^= 1; }
        else         { mwait(mb + 8, pf1); pf1 ^= 1; }

        // early prefetch of ||e||^2 for this ct (consumed in epilogue)
        const float2* cg = (const float2*)(g_c + ct * 128 + wc * 64 + ac * 2);
        float2 ccv[8];
#pragma unroll
        for (int u = 0; u < 8; ++u) ccv[u] = __ldg(&cg[u * 4]);

#pragma unroll
        for (int t = 0; t < 2; ++t)
#pragma unroll
            for (int u = 0; u < 8; ++u) { acc[t][u][0] = 0u; acc[t][u][1] = 0u; }

        const uint32_t stageOff = (uint32_t)st * 65536;
#pragma unroll
        for (int ksi = 0; ksi < 16; ++ksi) {
            const uint32_t ks = (uint32_t)(ksi ^ ksrev);          // stagger odd warps
            const uint32_t sub = (ks >> 2) * 16384;
            const uint32_t ksn = ks & 3;
            uint32_t a[2][4], bf[8][2];
#pragma unroll
            for (int t = 0; t < 2; ++t)
                ldsm4(a[t][0], a[t][1], a[t][2], a[t][3], aBase[t] + ks * 32);
#pragma unroll
            for (int up = 0; up < 4; ++up) {
                uint32_t addr = bBase[up] + stageOff + sub + ((ksn * 32 + kadd) ^ bXor[up]);
                ldsm4(bf[2 * up][0], bf[2 * up][1], bf[2 * up + 1][0], bf[2 * up + 1][1], addr);
            }
#pragma unroll
            for (int t = 0; t < 2; ++t)
#pragma unroll
                for (int u = 0; u < 8; ++u) mma16816h(acc[t][u], a[t], bf[u]);
        }

        // ---- epilogue: keys = c - 2*s ; per-thread top-2 over 16 owned codes/row ----
        {
            const int idx_base = ct * 128 + wc * 64 + ac * 2;
#pragma unroll
            for (int t = 0; t < 2; ++t) {
#pragma unroll
                for (int h = 0; h < 2; ++h) {
                    const int r = t * 2 + h;
                    float key[16];
#pragma unroll
                    for (int u = 0; u < 8; ++u) {
                        float2 f = __half22float2(*(__half2*)&acc[t][u][h]);
                        key[2 * u]     = fmaf(-2.f, f.x, ccv[u].x);
                        key[2 * u + 1] = fmaf(-2.f, f.y, ccv[u].y);
                    }
                    float tmin = key[0];
#pragma unroll
                    for (int j = 1; j < 16; ++j) tmin = fminf(tmin, key[j]);
                    if (tmin < m2f[r]) {
#pragma unroll
                        for (int j = 0; j < 16; ++j) {
                            float kj = key[j];
                            int   id = idx_base + (j >> 1) * 8 + (j & 1);
                            if (kj < m2f[r]) {
                                if (kj < m1f[r]) {
                                    m2f[r] = m1f[r]; m2i[r] = m1i[r];
                                    m1f[r] = kj;     m1i[r] = id;
                                } else { m2f[r] = kj; m2i[r] = id; }
                            }
                        }
                    }
                }
            }
        }

        __syncthreads();   // all warps done with stage st
        if (tid == 0 && ct < 62) {
            mbar_expect_tx(mb + st * 8, 65536);
            bulkcp(base + SM_B + (uint32_t)st * 65536,
                   g_embB + (size_t)(ct + 2) * 65536, 65536, mb + st * 8);
        }
    }

    // ---- candidate writeback: 8 owner threads x top2 = 16 per token ----
    __syncthreads();
#pragma unroll
    for (int t = 0; t < 2; ++t)
#pragma unroll
        for (int h = 0; h < 2; ++h) {
            int r = t * 2 + h;
            int row = wr * 32 + t * 16 + h * 8 + (lane >> 2);
            int slot = wc * 8 + (lane & 3) * 2;
            sCand[row * 16 + slot]     = (uint32_t)m1i[r];
            sCand[row * 16 + slot + 1] = (uint32_t)m2i[r];
        }
    if (tid < 128) sPack[tid] = ~0ULL;
    __syncthreads();

    // ---- exact fp32 rescore: thread -> (row = tid>>1, 8 cands) ----
    {
        const int row = tid >> 1, cb = (tid & 1) * 8;
        const float* zrow = Ag + row;
        int cidx[8];
        float ds[8];
#pragma unroll
        for (int c = 0; c < 8; ++c) { cidx[c] = (int)sCand[row * 16 + cb + c]; ds[c] = 0.f; }
#pragma unroll 4
        for (int blk = 0; blk < 32; ++blk) {
            float zb[8];
#pragma unroll
            for (int q = 0; q < 8; ++q) zb[q] = zrow[(size_t)(blk * 8 + q) * HWSZ];
#pragma unroll
            for (int c = 0; c < 8; ++c) {
                const float4* er = (const float4*)(emb + (size_t)cidx[c] * DD + blk * 8);
                float4 e0 = er[0], e1 = er[1];
                float s = ds[c];
                s = fmaf(e0.x, zb[0], s); s = fmaf(e0.y, zb[1], s);
                s = fmaf(e0.z, zb[2], s); s = fmaf(e0.w, zb[3], s);
                s = fmaf(e1.x, zb[4], s); s = fmaf(e1.y, zb[5], s);
                s = fmaf(e1.z, zb[6], s); s = fmaf(e1.w, zb[7], s);
                ds[c] = s;
            }
        }
        unsigned long long best = ~0ULL;
#pragma unroll
        for (int c = 0; c < 8; ++c) {
            float key = g_c[cidx[c]] - 2.f * ds[c];
            unsigned u = __float_as_uint(key);
            u = (u & 0x80000000u) ? ~u : (u | 0x80000000u);
            unsigned long long p = ((unsigned long long)u << 32) | (unsigned)cidx[c];
            best = (p < best) ? p : best;
        }
        atomicMin(&sPack[row], best);
    }
    __syncthreads();
    if (tid < 128) {
        uint32_t idx = (uint32_t)(sPack[tid] & 0xFFFFFFFFULL);
        sBest[tid] = idx;
        out[QSIZE + 1 + m0 + tid] = (float)idx;
    }
    __syncthreads();

    // ---- gather + quantized write (BCHW) + loss partial ----
    {
        const int t  = tid & 127;
        const int dh = tid >> 7;
        const int idx = (int)sBest[t];
        const float* erow = emb + (size_t)idx * DD + dh * 128;
        const float* xcol = Ag + (size_t)dh * 128 * HWSZ + t;
        float* qout = out + ((size_t)b * DD) * HWSZ + hw0 + (size_t)dh * 128 * HWSZ + t;
        float lsum = 0.f;
#pragma unroll 8
        for (int dn = 0; dn < 128; ++dn) {
            float q  = erow[dn];
            float zz = xcol[(size_t)dn * HWSZ];
            float df = q - zz;
            lsum += df * df;
            qout[(size_t)dn * HWSZ] = q;
        }
#pragma unroll
        for (int o = 16; o > 0; o >>= 1) lsum += __shfl_xor_sync(0xffffffffu, lsum, o);
        if ((tid & 31) == 0) atomicAdd(&g_loss, lsum);
    }

    // ---- folded finalize: last CTA writes the loss scalar ----
    __syncthreads();
    if (tid == 0) {
        __threadfence();
        unsigned old = atomicAdd(&g_done, 1u);
        if (old == (unsigned)(gridDim.x - 1)) {
            float total = atomicAdd(&g_loss, 0.f);
            out[QSIZE] = 1.25f * total * (1.0f / (float)QSIZE);
        }
    }
}

extern "C" void kernel_launch(void* const* d_in, const int* in_sizes, int n_in,
                              void* d_out, int out_size) {
    const float* x   = (const float*)d_in[0];
    const float* emb = (const float*)d_in[1];
    float* out = (float*)d_out;

    cudaFuncSetAttribute(vq_main, cudaFuncAttributeMaxDynamicSharedMemorySize, SMEM_BYTES);

    prep_all<<<1024, 256>>>(emb);
    vq_main<<<NTOK / 128, 256, SMEM_BYTES>>>(x, emb, out);
}

// round 14
// speedup vs baseline: 1.2325x; 1.2325x over previous
#include <cuda_runtime.h>
#include <cuda_fp16.h>
#include <cstdint>

#define DD    256
#define KK    8192
#define NTOK  16384
#define HWSZ  1024
#define QSIZE 4194304
// out layout: [quantized (QSIZE) | loss (1) | indices (NTOK)] fp32 (confirmed R1/R3/R6)

__device__ __align__(16) unsigned char g_embB[KK * DD * 2];  // 4MB pre-swizzled fp16 chunk blobs
__device__ float  g_c[KK];           // exact ||e_k||^2
__device__ float  g_loss;
__device__ unsigned g_done;

// ---- smem byte offsets (M=128 tile, 3-stage x 32KB bulk ring) ----
#define SM_A     0                // 128 rows x 528B = 67584
#define SM_B     67584            // 3 stages x 32768 = 98304
#define SM_MBAR  165888           // full[3] @ +0,+8,+16 ; cons[3] @ +24,+32,+40 (pad 64)
#define SM_PACK  165952           // u64[128] = 1024
#define SM_CAND  166976           // u32[2048] = 8192
#define SM_BEST  175168           // u32[128] = 512
#define SMEM_BYTES 175680

// ---------------- helpers ----------------
__device__ __forceinline__ uint32_t smem_u32(const void* p) {
    uint32_t a;
    asm("{ .reg .u64 t; cvta.to.shared.u64 t, %1; cvt.u32.u64 %0, t; }" : "=r"(a) : "l"(p));
    return a;
}
__device__ __forceinline__ void mbar_init(uint32_t mbar, uint32_t cnt) {
    asm volatile("mbarrier.init.shared.b64 [%0], %1;" :: "r"(mbar), "r"(cnt) : "memory");
}
__device__ __forceinline__ void mbar_expect_tx(uint32_t mbar, uint32_t tx) {
    asm volatile("mbarrier.arrive.expect_tx.shared.b64 _, [%0], %1;" :: "r"(mbar), "r"(tx) : "memory");
}
__device__ __forceinline__ void mbar_arrive(uint32_t mbar) {
    asm volatile("mbarrier.arrive.shared.b64 _, [%0];" :: "r"(mbar) : "memory");
}
__device__ __forceinline__ void mwait(uint32_t mbar, uint32_t ph) {
    uint32_t done = 0;
    while (!done)
        asm volatile("{ .reg .pred p; mbarrier.try_wait.parity.shared.b64 p, [%1], %2; selp.b32 %0,1,0,p; }"
                     : "=r"(done) : "r"(mbar), "r"(ph) : "memory");
}
__device__ __forceinline__ void bulkcp(uint32_t dst, const void* src, uint32_t bytes, uint32_t mbar) {
    asm volatile("cp.async.bulk.shared::cluster.global.mbarrier::complete_tx::bytes [%0], [%1], %2, [%3];"
                 :: "r"(dst), "l"(src), "r"(bytes), "r"(mbar) : "memory");
}
__device__ __forceinline__ void ldsm4(uint32_t& r0, uint32_t& r1, uint32_t& r2, uint32_t& r3,
                                      uint32_t addr) {
    asm volatile("ldmatrix.sync.aligned.m8n8.x4.shared.b16 {%0,%1,%2,%3}, [%4];"
                 : "=r"(r0), "=r"(r1), "=r"(r2), "=r"(r3) : "r"(addr));
}
// f16-accumulate MMA: D/C = 2 regs (4 halves)
__device__ __forceinline__ void mma16816h(uint32_t* d, const uint32_t* a, const uint32_t* b) {
    asm volatile("mma.sync.aligned.m16n8k16.row.col.f16.f16.f16.f16 "
                 "{%0,%1},{%2,%3,%4,%5},{%6,%7},{%0,%1};"
                 : "+r"(d[0]), "+r"(d[1])
                 : "r"(a[0]), "r"(a[1]), "r"(a[2]), "r"(a[3]), "r"(b[0]), "r"(b[1]));
}

// ---------------- prep: emb -> swizzled fp16 chunk blobs + ||e||^2 ----------------
// 16KB sub-chunk c = (ct*4+kc). Byte for (code n, seg of 8 halves):
//   c*16384 + n*128 + ((seg*16) ^ ((n&7)*16))
__global__ void prep_all(const float* __restrict__ emb) {
    const int gid = blockIdx.x * 256 + threadIdx.x;    // 1024 blocks -> 262144 threads
    const int k = gid >> 5, r5 = gid & 31;             // one warp per code k
    const int kc = r5 >> 3, seg = r5 & 7;
    const int n = k & 127, ct = k >> 7;
    const float4* src = (const float4*)(emb + (size_t)k * DD + kc * 64 + seg * 8);
    float4 f0 = src[0], f1 = src[1];
    __half2 h01 = __floats2half2_rn(f0.x, f0.y);
    __half2 h23 = __floats2half2_rn(f0.z, f0.w);
    __half2 h45 = __floats2half2_rn(f1.x, f1.y);
    __half2 h67 = __floats2half2_rn(f1.z, f1.w);
    uint4 pack;
    pack.x = *(uint32_t*)&h01; pack.y = *(uint32_t*)&h23;
    pack.z = *(uint32_t*)&h45; pack.w = *(uint32_t*)&h67;
    uint32_t off = (uint32_t)((ct * 4 + kc) << 14) + (uint32_t)(n * 128)
                 + (((uint32_t)seg * 16) ^ ((uint32_t)(n & 7) * 16));
    *(uint4*)(g_embB + off) = pack;

    float s = f0.x*f0.x + f0.y*f0.y + f0.z*f0.z + f0.w*f0.w
            + f1.x*f1.x + f1.y*f1.y + f1.z*f1.z + f1.w*f1.w;
#pragma unroll
    for (int o = 16; o > 0; o >>= 1) s += __shfl_xor_sync(0xffffffffu, s, o);
    if (r5 == 0) g_c[k] = s;
    if (gid == 0) { g_loss = 0.f; g_done = 0u; }
}

// ---------------- main: M=128, 128 CTAs x 256 thr, 3-stage 32KB ring, no per-chunk barrier ----------------
__global__ void __launch_bounds__(256, 1) vq_main(const float* __restrict__ x,
                                                  const float* __restrict__ emb,
                                                  float* __restrict__ out) {
    extern __shared__ __align__(128) char sm[];
    const uint32_t base = smem_u32(sm);

    unsigned long long* sPack = (unsigned long long*)(sm + SM_PACK);
    uint32_t* sCand = (uint32_t*)(sm + SM_CAND);
    uint32_t* sBest = (uint32_t*)(sm + SM_BEST);
    const uint32_t mbF = base + SM_MBAR;        // full[3]
    const uint32_t mbC = base + SM_MBAR + 24;   // cons[3]

    const int tid = threadIdx.x, lane = tid & 31, wid = tid >> 5;
    const int wr = wid >> 1, wc = wid & 1;            // 4 warp-rows x 2 warp-cols
    const int m0 = blockIdx.x * 128, b = m0 >> 10, hw0 = m0 & 1023;
    const float* Ag = x + (size_t)b * DD * HWSZ + hw0;   // Ag[d*1024 + token]

    if (tid == 0) {
        mbar_init(mbF + 0, 1); mbar_init(mbF + 8, 1); mbar_init(mbF + 16, 1);
        mbar_init(mbC + 0, 8); mbar_init(mbC + 8, 8); mbar_init(mbC + 16, 8);
        asm volatile("fence.proxy.async.shared::cta;" ::: "memory");
    }

    // ---- build A smem [token][k] fp16 (row stride 264 halves = 528B) ----
#pragma unroll 4
    for (int it = 0; it < 64; ++it) {
        int i  = tid + it * 256;            // 0..16383
        int dp = i >> 7, r = i & 127;       // dp = d-pair 0..127, r = token 0..127
        float v0 = Ag[(size_t)(2 * dp) * HWSZ + r];
        float v1 = Ag[(size_t)(2 * dp + 1) * HWSZ + r];
        __half2 h2 = __floats2half2_rn(v0, v1);
        *(uint32_t*)(sm + SM_A + r * 528 + dp * 4) = *(uint32_t*)&h2;
    }
    __syncthreads();   // mbar init + A visible

    // ---- prefetch big-chunks 0,1 into stages 0,1 ----
    if (tid == 0) {
#pragma unroll
        for (int c = 0; c < 2; ++c) {
            mbar_expect_tx(mbF + c * 8, 32768);
            bulkcp(base + SM_B + (uint32_t)c * 32768, g_embB + (size_t)c * 32768, 32768, mbF + c * 8);
        }
    }

    // ---- precomputed ldmatrix addresses ----
    const int i8 = lane & 7, g = lane >> 3;
    uint32_t aBase[2];
#pragma unroll
    for (int t = 0; t < 2; ++t) {
        int rowA = wr * 32 + t * 16 + (g & 1) * 8 + i8;
        aBase[t] = base + SM_A + rowA * 528 + (g >> 1) * 16;
    }
    uint32_t bBase[4], bXor[4];
    const uint32_t kadd = (g & 1) * 16;
#pragma unroll
    for (int up = 0; up < 4; ++up) {
        int n = wc * 64 + up * 16 + ((g >> 1) ? 8 : 0) + i8;
        bBase[up] = base + SM_B + n * 128;
        bXor[up]  = (uint32_t)((n & 7) * 16);
    }

    uint32_t acc[2][8][2];                 // f16x2 accumulators
    const float INF = __int_as_float(0x7f800000);
    float m1f[4] = {INF, INF, INF, INF}, m2f[4] = {INF, INF, INF, INF};
    int   m1i[4] = {0, 0, 0, 0},        m2i[4] = {0, 0, 0, 0};
    const int ac = lane & 3;
    uint32_t pf0 = 0, pf1 = 0, pf2 = 0;          // full-barrier phases (per warp)
    uint32_t pc0 = 0, pc1 = 0, pc2 = 0;          // cons-barrier phases (tid0 only)

    for (int big = 0; big < 128; ++big) {     // big-chunk = 128 codes x 128 dims (32KB)
        const int st = big % 3;

        // producer: wait stage (big+2)%3 consumed, then overwrite with chunk big+2
        if (tid == 0 && big < 126) {
            int c = big + 2, s2 = c % 3;
            if (c >= 3) {
                if (s2 == 0)      { mwait(mbC + 0,  pc0); pc0 ^= 1; }
                else if (s2 == 1) { mwait(mbC + 8,  pc1); pc1 ^= 1; }
                else              { mwait(mbC + 16, pc2); pc2 ^= 1; }
            }
            mbar_expect_tx(mbF + s2 * 8, 32768);
            bulkcp(base + SM_B + (uint32_t)s2 * 32768, g_embB + (size_t)c * 32768, 32768, mbF + s2 * 8);
        }

        // consumer: wait this chunk's bulk copy
        if (st == 0)      { mwait(mbF + 0,  pf0); pf0 ^= 1; }
        else if (st == 1) { mwait(mbF + 8,  pf1); pf1 ^= 1; }
        else              { mwait(mbF + 16, pf2); pf2 ^= 1; }

        if (!(big & 1)) {
#pragma unroll
            for (int t = 0; t < 2; ++t)
#pragma unroll
                for (int u = 0; u < 8; ++u) { acc[t][u][0] = 0u; acc[t][u][1] = 0u; }
        }

        const uint32_t stageOff = (uint32_t)st * 32768;
        const uint32_t kbA0 = (uint32_t)(big & 1) * 256;   // dim-half offset in A row (bytes)
#pragma unroll
        for (int ks = 0; ks < 8; ++ks) {
            const uint32_t sub = (uint32_t)(ks >> 2) * 16384;
            const uint32_t ksn = (uint32_t)(ks & 3);
            uint32_t a[2][4], bf[8][2];
#pragma unroll
            for (int t = 0; t < 2; ++t)
                ldsm4(a[t][0], a[t][1], a[t][2], a[t][3], aBase[t] + kbA0 + ks * 32);
#pragma unroll
            for (int up = 0; up < 4; ++up) {
                uint32_t addr = bBase[up] + stageOff + sub + ((ksn * 32 + kadd) ^ bXor[up]);
                ldsm4(bf[2 * up][0], bf[2 * up][1], bf[2 * up + 1][0], bf[2 * up + 1][1], addr);
            }
#pragma unroll
            for (int t = 0; t < 2; ++t)
#pragma unroll
                for (int u = 0; u < 8; ++u) mma16816h(acc[t][u], a[t], bf[u]);
        }

        // this warp is done reading stage st (LDSM results consumed by MMAs in program order)
        if (lane == 0) mbar_arrive(mbC + st * 8);

        if (big & 1) {
            // keys = c - 2*s ; per-thread top-2 over this ct's 16 owned codes/row
            const int ct = big >> 1;
            const float2* cg = (const float2*)(g_c + ct * 128 + wc * 64 + ac * 2);
            float2 ccv[8];
#pragma unroll
            for (int u = 0; u < 8; ++u) ccv[u] = __ldg(&cg[u * 4]);
            const int idx_base = ct * 128 + wc * 64 + ac * 2;
#pragma unroll
            for (int t = 0; t < 2; ++t) {
#pragma unroll
                for (int h = 0; h < 2; ++h) {
                    const int r = t * 2 + h;
                    float key[16];
#pragma unroll
                    for (int u = 0; u < 8; ++u) {
                        float2 f = __half22float2(*(__half2*)&acc[t][u][h]);
                        key[2 * u]     = fmaf(-2.f, f.x, ccv[u].x);
                        key[2 * u + 1] = fmaf(-2.f, f.y, ccv[u].y);
                    }
                    float tmin = key[0];
#pragma unroll
                    for (int j = 1; j < 16; ++j) tmin = fminf(tmin, key[j]);
                    if (tmin < m2f[r]) {
#pragma unroll
                        for (int j = 0; j < 16; ++j) {
                            float kj = key[j];
                            int   id = idx_base + (j >> 1) * 8 + (j & 1);
                            if (kj < m2f[r]) {
                                if (kj < m1f[r]) {
                                    m2f[r] = m1f[r]; m2i[r] = m1i[r];
                                    m1f[r] = kj;     m1i[r] = id;
                                } else { m2f[r] = kj; m2i[r] = id; }
                            }
                        }
                    }
                }
            }
        }
    }

    // ---- candidate writeback: 8 owner threads x top2 = 16 per token ----
    __syncthreads();
#pragma unroll
    for (int t = 0; t < 2; ++t)
#pragma unroll
        for (int h = 0; h < 2; ++h) {
            int r = t * 2 + h;
            int row = wr * 32 + t * 16 + h * 8 + (lane >> 2);
            int slot = wc * 8 + (lane & 3) * 2;
            sCand[row * 16 + slot]     = (uint32_t)m1i[r];
            sCand[row * 16 + slot + 1] = (uint32_t)m2i[r];
        }
    if (tid < 128) sPack[tid] = ~0ULL;
    __syncthreads();

    // ---- exact fp32 rescore: thread -> (row = tid>>1, 8 cands) ----
    {
        const int row = tid >> 1, cb = (tid & 1) * 8;
        const float* zrow = Ag + row;
        int cidx[8];
        float ds[8];
#pragma unroll
        for (int c = 0; c < 8; ++c) { cidx[c] = (int)sCand[row * 16 + cb + c]; ds[c] = 0.f; }
#pragma unroll 4
        for (int blk = 0; blk < 32; ++blk) {
            float zb[8];
#pragma unroll
            for (int q = 0; q < 8; ++q) zb[q] = zrow[(size_t)(blk * 8 + q) * HWSZ];
#pragma unroll
            for (int c = 0; c < 8; ++c) {
                const float4* er = (const float4*)(emb + (size_t)cidx[c] * DD + blk * 8);
                float4 e0 = er[0], e1 = er[1];
                float s = ds[c];
                s = fmaf(e0.x, zb[0], s); s = fmaf(e0.y, zb[1], s);
                s = fmaf(e0.z, zb[2], s); s = fmaf(e0.w, zb[3], s);
                s = fmaf(e1.x, zb[4], s); s = fmaf(e1.y, zb[5], s);
                s = fmaf(e1.z, zb[6], s); s = fmaf(e1.w, zb[7], s);
                ds[c] = s;
            }
        }
        unsigned long long best = ~0ULL;
#pragma unroll
        for (int c = 0; c < 8; ++c) {
            float key = g_c[cidx[c]] - 2.f * ds[c];
            unsigned u = __float_as_uint(key);
            u = (u & 0x80000000u) ? ~u : (u | 0x80000000u);
            unsigned long long p = ((unsigned long long)u << 32) | (unsigned)cidx[c];
            best = (p < best) ? p : best;
        }
        atomicMin(&sPack[row], best);
    }
    __syncthreads();
    if (tid < 128) {
        uint32_t idx = (uint32_t)(sPack[tid] & 0xFFFFFFFFULL);
        sBest[tid] = idx;
        out[QSIZE + 1 + m0 + tid] = (float)idx;
    }
    __syncthreads();

    // ---- gather + quantized write (BCHW) + loss partial ----
    {
        const int t  = tid & 127;
        const int dh = tid >> 7;
        const int idx = (int)sBest[t];
        const float* erow = emb + (size_t)idx * DD + dh * 128;
        const float* xcol = Ag + (size_t)dh * 128 * HWSZ + t;
        float* qout = out + ((size_t)b * DD) * HWSZ + hw0 + (size_t)dh * 128 * HWSZ + t;
        float lsum = 0.f;
#pragma unroll 8
        for (int dn = 0; dn < 128; ++dn) {
            float q  = erow[dn];
            float zz = xcol[(size_t)dn * HWSZ];
            float df = q - zz;
            lsum += df * df;
            qout[(size_t)dn * HWSZ] = q;
        }
#pragma unroll
        for (int o = 16; o > 0; o >>= 1) lsum += __shfl_xor_sync(0xffffffffu, lsum, o);
        if ((tid & 31) == 0) atomicAdd(&g_loss, lsum);
    }

    // ---- folded finalize: last CTA writes the loss scalar ----
    __syncthreads();
    if (tid == 0) {
        __threadfence();
        unsigned old = atomicAdd(&g_done, 1u);
        if (old == (unsigned)(gridDim.x - 1)) {
            float total = atomicAdd(&g_loss, 0.f);
            out[QSIZE] = 1.25f * total * (1.0f / (float)QSIZE);
        }
    }
}

extern "C" void kernel_launch(void* const* d_in, const int* in_sizes, int n_in,
                              void* d_out, int out_size) {
    const float* x   = (const float*)d_in[0];
    const float* emb = (const float*)d_in[1];
    float* out = (float*)d_out;

    cudaFuncSetAttribute(vq_main, cudaFuncAttributeMaxDynamicSharedMemorySize, SMEM_BYTES);

    prep_all<<<1024, 256>>>(emb);
    vq_main<<<NTOK / 128, 256, SMEM_BYTES>>>(x, emb, out);
}